// round 16
// baseline (speedup 1.0000x reference)
#include <cuda_runtime.h>
#include <cuda_fp16.h>
#include <math.h>
#include <cstdint>

#define DM 128
#define NN 65536
#define NC 440   // persistent grid; 440 = 8*55 <= 3 CTAs/SM x 148 SMs (co-resident)

// ---------------- device scratch (module globals; no runtime alloc) --------
__device__ float    g_c[NN * DM];              // cell state fp32 (leaf c implicit 0)
__device__ __half   g_h[(NN + 512) * DM];      // hidden fp16; pad rows (tile overread)
__device__ __half   g_wt[640 * 256];           // W_bin^T fp16 [n][k]
__device__ unsigned g_flag[10 * 64];           // dataflow counters [level][chunk256]
__device__ unsigned g_cnt[4];                  // grid barrier arrivals
__device__ unsigned g_gen[4];                  // grid barrier generations (monotonic)

// tanh.approx.f32: single MUFU op (sm_75+, not arch-'a' gated)
__device__ __forceinline__ float tanhapx(float x) {
    float y;
    asm("tanh.approx.f32 %0, %1;" : "=f"(y) : "f"(x));
    return y;
}
// sigmoid via tanh: sig(x) = 0.5*tanh(x/2) + 0.5   (1 MUFU + 2 FMA)
__device__ __forceinline__ float sigf(float x) {
    return fmaf(0.5f, tanhapx(0.5f * x), 0.5f);
}

// mma.sync m16n8k16 fp16 -> f32
#define MMA(acc, a, b0, b1)                                                     \
    asm volatile("mma.sync.aligned.m16n8k16.row.col.f32.f16.f16.f32 "           \
                 "{%0,%1,%2,%3}, {%4,%5,%6,%7}, {%8,%9}, {%0,%1,%2,%3};"        \
                 : "+f"((acc)[0]), "+f"((acc)[1]), "+f"((acc)[2]), "+f"((acc)[3]) \
                 : "r"((a)[0]), "r"((a)[1]), "r"((a)[2]), "r"((a)[3]),          \
                   "r"(b0), "r"(b1))

// B smem: 80 rows (5 gates x 16 dims) x 512B, stride 576 (conflict-free LDS.128)
#define SBSTR 576
#define SBTOT (80 * SBSTR)   // 46080 B

// grid-wide barrier (used once: after flag zero + W prep + leaves)
__device__ __forceinline__ void grid_bar(int b) {
    __syncthreads();
    if (threadIdx.x == 0) {
        __threadfence();
        unsigned my = ((volatile unsigned*)g_gen)[b];
        unsigned old = atomicAdd(&g_cnt[b], 1u);
        if (old == (unsigned)(NC - 1)) {
            g_cnt[b] = 0;
            __threadfence();
            atomicAdd(&g_gen[b], 1u);
        } else {
            while (((volatile unsigned*)g_gen)[b] == my) { }
        }
        __threadfence();
    }
    __syncthreads();
}

// produce: all stores visible, then bump chunk counter (one atomic per CTA)
__device__ __forceinline__ void produce(int lvl, int chunk) {
    __threadfence();
    __syncthreads();
    if (threadIdx.x == 0) atomicAdd(&g_flag[lvl * 64 + chunk], 1u);
}
// consume: spin until chunk counter reaches target
__device__ __forceinline__ void consume(int lvl, int chunk, unsigned tgt) {
    if (threadIdx.x == 0) {
        volatile unsigned* f = &g_flag[lvl * 64 + chunk];
        while (*f < tgt) { }
        __threadfence();
    }
    __syncthreads();
}

// ---------------------------------------------------------------------------
// ONE persistent kernel, 3 CTAs/SM. Leaves strided over ALL CTAs before the
// single grid barrier (no leaf flags). Levels 2..9 gated by per-(level,
// 256-node-chunk) dataflow counters. B tile (dp=cta&7) staged once.
// ---------------------------------------------------------------------------
__global__ void __launch_bounds__(256, 3)
fused(const int* __restrict__ tokens, const float* __restrict__ emb,
      const float* __restrict__ Wu, const float* __restrict__ bu,
      const float* __restrict__ Wb, const float* __restrict__ bbin,
      float* __restrict__ out) {
    __shared__ __align__(16) char sB[SBTOT];
    __shared__ __align__(16) float sBB[640];
    int t = threadIdx.x, cta = blockIdx.x;
    int wid = t >> 5, lane = t & 31;
    int g = lane >> 2, i = lane & 3;

    // ---- pre-barrier phase: flags, W transpose, biases, ALL leaves
    for (int idx = t; idx < 640; idx += 256) g_flag[idx] = 0u;
    for (int idx = cta * 256 + t; idx < 256 * 640; idx += NC * 256) {
        int k = idx / 640, n = idx % 640;
        g_wt[n * 256 + k] = __float2half(Wb[idx]);
    }
    for (int idx = t; idx < 640; idx += 256) sBB[idx] = bbin[idx];

    // leaves: one warp per node, strided over all NC CTAs (no flags needed)
#pragma unroll 4
    for (int n = cta * 8 + wid; n < 32768; n += NC * 8) {
        int tok = tokens[n];
        float4 e = ((const float4*)emb)[tok * 32 + lane];
        float ss = e.x * e.x + e.y * e.y + e.z * e.z + e.w * e.w;
#pragma unroll
        for (int o = 16; o; o >>= 1) ss += __shfl_xor_sync(0xffffffffu, ss, o);
        float nrm = sqrtf(ss);
        float sc = nrm > 1.0f ? 1.0f / nrm : 1.0f;
        float hv[4] = {e.x * sc, e.y * sc, e.z * sc, e.w * sc};
        __half2* hp = (__half2*)(g_h + n * DM + lane * 4);
        hp[0] = __floats2half2_rn(hv[0], hv[1]);
        hp[1] = __floats2half2_rn(hv[2], hv[3]);
        int b = n >> 9, j = n & 511;
        ((float4*)out)[(b * 1024 + j) * 32 + lane] =
            make_float4(hv[0], hv[1], hv[2], hv[3]);
    }
    grid_bar(0);   // after this: W, biases, leaves, zeroed flags all visible

    int dp = cta & 7;                          // d-group: invariant for whole run
    // ---- stage B ONCE
#pragma unroll
    for (int it = 0; it < 10; it++) {
        int idx = it * 256 + t;
        int rr = idx >> 5, w = idx & 31;
        int grow = (rr >> 4) * 128 + dp * 16 + (rr & 15);
        *(uint4*)(sB + rr * SBSTR + w * 16) =
            *(const uint4*)(g_wt + grow * 256 + w * 8);
    }
    __syncthreads();

    uint32_t arow = (uint32_t)(wid * 16 + g) * 512u + (uint32_t)i * 16u;

    // ---- binary levels 1..9 (dataflow; level 1 needs no consume)
#pragma unroll 1
    for (int l = 1; l <= 9; l++) {
        int M       = 32768 >> l;
        int s       = 65536 - (65536 >> l);
        int Gc      = 65536 - (65536 >> (l - 1));
        int cshift  = 9 - l;
        int offl    = 1024 - (1024 >> l);
        int czero   = (l == 1);
        int ntm     = (M >= 128) ? (M >> 7) : 1;
        int ntile   = ntm * 8;
        int ntmprev = (((32768 >> (l - 1)) >= 128) ? ((32768 >> (l - 1)) >> 7) : 1);

#pragma unroll 1
        for (int tb = cta; tb < ntile; tb += NC) {
            int tm = tb >> 3;                  // dp == cta & 7 (NC % 8 == 0)
            int m0 = tm * 128;
            if (l > 1) {
                unsigned tgt = 8u * (unsigned)((ntmprev - 2 * tm) >= 2 ? 2
                                               : (ntmprev - 2 * tm));
                consume(l - 1, tm, tgt);
            }

            const char* A = (const char*)g_h + (size_t)(Gc + 2 * m0) * 256;

            float acc[5][2][4];
#pragma unroll
            for (int q = 0; q < 5; q++)
#pragma unroll
                for (int dh = 0; dh < 2; dh++)
#pragma unroll
                    for (int c = 0; c < 4; c++) acc[q][dh][c] = 0.f;

#pragma unroll
            for (int pr = 0; pr < 8; pr++) {
                uint4 a0 = *(const uint4*)(A + arow + (uint32_t)pr * 64u);
                uint4 a1 = *(const uint4*)(A + arow + 8u * 512u + (uint32_t)pr * 64u);
                uint32_t f0[4] = {a0.x, a1.x, a0.y, a1.y};
                uint32_t f1[4] = {a0.z, a1.z, a0.w, a1.w};
#pragma unroll
                for (int q = 0; q < 5; q++) {
#pragma unroll
                    for (int dh = 0; dh < 2; dh++) {
                        uint4 b = *(const uint4*)(sB + (q * 16 + dh * 8 + g) * SBSTR
                                                  + i * 16 + pr * 64);
                        MMA(acc[q][dh], f0, b.x, b.y);
                        MMA(acc[q][dh], f1, b.z, b.w);
                    }
                }
            }

            // epilogue: thread covers rows {g, g+8} x dims {dh*8 + 2i, +1}
#pragma unroll
            for (int rh = 0; rh < 2; rh++) {
                int lm = wid * 16 + rh * 8 + g;
                if (m0 + lm >= M) continue;
                int node = s + m0 + lm;
                int ch = Gc + 2 * (m0 + lm);
                int local = m0 + lm;
                int b = local >> cshift;
                int jj = local & ((1 << cshift) - 1);
                size_t orow = ((size_t)(b * 1024 + offl + jj)) * DM;
#pragma unroll
                for (int dh = 0; dh < 2; dh++) {
                    int dd = dp * 16 + dh * 8 + i * 2;
                    float2 cl = make_float2(0.f, 0.f), cr = make_float2(0.f, 0.f);
                    if (!czero) {
                        cl = *(const float2*)(g_c + (size_t)ch * DM + dd);
                        cr = *(const float2*)(g_c + (size_t)(ch + 1) * DM + dd);
                    }
                    float hv[2], cv[2];
#pragma unroll
                    for (int e = 0; e < 2; e++) {
                        float gi = acc[0][dh][rh * 2 + e] + sBB[0 * 128 + dd + e];
                        float go = acc[1][dh][rh * 2 + e] + sBB[1 * 128 + dd + e];
                        float gu = acc[2][dh][rh * 2 + e] + sBB[2 * 128 + dd + e];
                        float gl = acc[3][dh][rh * 2 + e] + sBB[3 * 128 + dd + e];
                        float gr = acc[4][dh][rh * 2 + e] + sBB[4 * 128 + dd + e];
                        float clv = e ? cl.y : cl.x;
                        float crv = e ? cr.y : cr.x;
                        float c = sigf(gi) * tanhapx(gu)
                                + sigf(gl) * clv + sigf(gr) * crv;
                        cv[e] = c;
                        hv[e] = sigf(go) * tanhapx(c);
                    }
                    *(float2*)(g_c + (size_t)node * DM + dd) = make_float2(cv[0], cv[1]);
                    *(__half2*)(g_h + (size_t)node * DM + dd) =
                        __floats2half2_rn(hv[0], hv[1]);
                    *(float2*)(out + orow + dd) = make_float2(hv[0], hv[1]);
                }
            }
            produce(l, tm >> 1);
        }
    }

    // ---- unary top level: 64 nodes; wait for all 8 level-9 tiles
    if (cta < 64) {
        consume(9, 0, 8u);
        float* xh = (float*)sB;                // B tile dead by now
        int ch = 65408 + cta;
        if (t < 128) xh[t] = __half2float(g_h[ch * DM + t]);
        __syncthreads();
        if (t < 128) {
            float acc[4] = {0.f, 0.f, 0.f, 0.f};
            for (int k = 0; k < 128; k++) {
                float x = xh[k];
#pragma unroll
                for (int q = 0; q < 4; q++) acc[q] += x * Wu[k * 512 + q * 128 + t];
            }
            float cc = g_c[ch * DM + t];
            float gi = acc[0] + bu[t];
            float go = acc[1] + bu[128 + t];
            float gu = acc[2] + bu[256 + t];
            float gf = acc[3] + bu[384 + t];
            float c = sigf(gi) * tanhapx(gu) + sigf(gf) * cc;
            float h = sigf(go) * tanhapx(c);
            out[((size_t)(cta * 1024 + 1023)) * DM + t] = h;
        }
    }
}

// ---------------------------------------------------------------------------
// kernel_launch: ONE kernel launch (graph-capturable, replay-deterministic)
// ---------------------------------------------------------------------------
extern "C" void kernel_launch(void* const* d_in, const int* in_sizes, int n_in,
                              void* d_out, int out_size) {
    const int* tokens = (const int*)d_in[0];
    const float* emb  = (const float*)d_in[3];
    const float* Wu   = (const float*)d_in[4];
    const float* bu   = (const float*)d_in[5];
    const float* Wb   = (const float*)d_in[6];
    const float* bb   = (const float*)d_in[7];
    float* out = (float*)d_out;

    fused<<<NC, 256>>>(tokens, emb, Wu, bu, Wb, bb, out);
}

// round 17
// speedup vs baseline: 1.2776x; 1.2776x over previous
#include <cuda_runtime.h>
#include <cuda_fp16.h>
#include <math.h>
#include <cstdint>

#define DM 128
#define NN 65536
#define NC 296   // persistent grid; 296 = 8*37 = 2 CTAs/SM x 148 SMs (co-resident)

// ---------------- device scratch (module globals; no runtime alloc) --------
__device__ float    g_c[NN * DM];              // cell state fp32 (leaf c implicit 0)
__device__ __half   g_h[(NN + 512) * DM];      // hidden fp16; pad rows (tile overread)
__device__ __half   g_wt[640 * 256];           // W_bin^T fp16 [n][k]
__device__ unsigned g_flag[10 * 64];           // dataflow counters [level][chunk256]
__device__ unsigned g_cnt[4];                  // grid barrier arrivals
__device__ unsigned g_gen[4];                  // grid barrier generations (monotonic)

// tanh.approx.f32: single MUFU op (sm_75+, not arch-'a' gated)
__device__ __forceinline__ float tanhapx(float x) {
    float y;
    asm("tanh.approx.f32 %0, %1;" : "=f"(y) : "f"(x));
    return y;
}
// sigmoid via tanh: sig(x) = 0.5*tanh(x/2) + 0.5   (1 MUFU + 2 FMA)
__device__ __forceinline__ float sigf(float x) {
    return fmaf(0.5f, tanhapx(0.5f * x), 0.5f);
}

// mma.sync m16n8k16 fp16 -> f32
#define MMA(acc, a, b0, b1)                                                     \
    asm volatile("mma.sync.aligned.m16n8k16.row.col.f32.f16.f16.f32 "           \
                 "{%0,%1,%2,%3}, {%4,%5,%6,%7}, {%8,%9}, {%0,%1,%2,%3};"        \
                 : "+f"((acc)[0]), "+f"((acc)[1]), "+f"((acc)[2]), "+f"((acc)[3]) \
                 : "r"((a)[0]), "r"((a)[1]), "r"((a)[2]), "r"((a)[3]),          \
                   "r"(b0), "r"(b1))

// B smem: 80 rows (5 gates x 16 dims) x 512B, stride 576 (conflict-free LDS.128)
#define SBSTR 576
#define SBTOT (80 * SBSTR)   // 46080 B

// grid-wide barrier (used once: after flag zero + W prep + leaves)
__device__ __forceinline__ void grid_bar(int b) {
    __syncthreads();
    if (threadIdx.x == 0) {
        __threadfence();
        unsigned my = ((volatile unsigned*)g_gen)[b];
        unsigned old = atomicAdd(&g_cnt[b], 1u);
        if (old == (unsigned)(NC - 1)) {
            g_cnt[b] = 0;
            __threadfence();
            atomicAdd(&g_gen[b], 1u);
        } else {
            while (((volatile unsigned*)g_gen)[b] == my) { }
        }
        __threadfence();
    }
    __syncthreads();
}

// produce: all stores visible, then bump chunk counter (one atomic per CTA)
__device__ __forceinline__ void produce(int lvl, int chunk) {
    __threadfence();
    __syncthreads();
    if (threadIdx.x == 0) atomicAdd(&g_flag[lvl * 64 + chunk], 1u);
}
// consume: spin until chunk counter reaches target
__device__ __forceinline__ void consume(int lvl, int chunk, unsigned tgt) {
    if (threadIdx.x == 0) {
        volatile unsigned* f = &g_flag[lvl * 64 + chunk];
        while (*f < tgt) { }
        __threadfence();
    }
    __syncthreads();
}

// ---------------------------------------------------------------------------
// ONE persistent kernel (round-15 config). New: child-c prefetch before the
// MMA loop so the 160-MMA burst hides the cold g_c latency on every tile.
// ---------------------------------------------------------------------------
__global__ void __launch_bounds__(256, 2)
fused(const int* __restrict__ tokens, const float* __restrict__ emb,
      const float* __restrict__ Wu, const float* __restrict__ bu,
      const float* __restrict__ Wb, const float* __restrict__ bbin,
      float* __restrict__ out) {
    __shared__ __align__(16) char sB[SBTOT];
    __shared__ __align__(16) float sBB[640];
    int t = threadIdx.x, cta = blockIdx.x;
    int wid = t >> 5, lane = t & 31;
    int g = lane >> 2, i = lane & 3;

    // ---- pre-barrier phase: flags, W transpose, biases, ALL leaves
    for (int idx = t; idx < 640; idx += 256) g_flag[idx] = 0u;
    for (int idx = cta * 256 + t; idx < 256 * 640; idx += NC * 256) {
        int k = idx / 640, n = idx % 640;
        g_wt[n * 256 + k] = __float2half(Wb[idx]);
    }
    for (int idx = t; idx < 640; idx += 256) sBB[idx] = bbin[idx];

    if (cta < 256) {   // leaf items: CTA x owns nodes [x*128, x*128+128)
#pragma unroll 4
        for (int it = 0; it < 16; it++) {
            int n = cta * 128 + it * 8 + wid;
            int tok = tokens[n];
            float4 e = ((const float4*)emb)[tok * 32 + lane];
            float ss = e.x * e.x + e.y * e.y + e.z * e.z + e.w * e.w;
#pragma unroll
            for (int o = 16; o; o >>= 1) ss += __shfl_xor_sync(0xffffffffu, ss, o);
            float nrm = sqrtf(ss);
            float sc = nrm > 1.0f ? 1.0f / nrm : 1.0f;
            float hv[4] = {e.x * sc, e.y * sc, e.z * sc, e.w * sc};
            __half2* hp = (__half2*)(g_h + n * DM + lane * 4);
            hp[0] = __floats2half2_rn(hv[0], hv[1]);
            hp[1] = __floats2half2_rn(hv[2], hv[3]);
            int b = n >> 9, j = n & 511;
            ((float4*)out)[(b * 1024 + j) * 32 + lane] =
                make_float4(hv[0], hv[1], hv[2], hv[3]);
        }
    }
    grid_bar(0);   // after this: W, biases, leaves, zeroed flags all visible

    int dp = cta & 7;                          // d-group: invariant for whole run
    // ---- stage B ONCE
#pragma unroll
    for (int it = 0; it < 10; it++) {
        int idx = it * 256 + t;
        int rr = idx >> 5, w = idx & 31;
        int grow = (rr >> 4) * 128 + dp * 16 + (rr & 15);
        *(uint4*)(sB + rr * SBSTR + w * 16) =
            *(const uint4*)(g_wt + grow * 256 + w * 8);
    }
    __syncthreads();

    uint32_t arow = (uint32_t)(wid * 16 + g) * 512u + (uint32_t)i * 16u;

    // ---- binary levels 1..9 (dataflow; level 1 needs no consume)
#pragma unroll 1
    for (int l = 1; l <= 9; l++) {
        int M       = 32768 >> l;
        int s       = 65536 - (65536 >> l);
        int Gc      = 65536 - (65536 >> (l - 1));
        int cshift  = 9 - l;
        int offl    = 1024 - (1024 >> l);
        int czero   = (l == 1);
        int ntm     = (M >= 128) ? (M >> 7) : 1;
        int ntile   = ntm * 8;
        int ntmprev = (((32768 >> (l - 1)) >= 128) ? ((32768 >> (l - 1)) >> 7) : 1);

#pragma unroll 1
        for (int tb = cta; tb < ntile; tb += NC) {
            int tm = tb >> 3;                  // dp == cta & 7 (NC % 8 == 0)
            int m0 = tm * 128;
            if (l > 1) {
                unsigned tgt = 8u * (unsigned)((ntmprev - 2 * tm) >= 2 ? 2
                                               : (ntmprev - 2 * tm));
                consume(l - 1, tm, tgt);
            }

            const char* A = (const char*)g_h + (size_t)(Gc + 2 * m0) * 256;

            // ---- prefetch child c (hidden behind the 160-MMA burst below)
            float2 pcl[2][2], pcr[2][2];       // [rh][dh]
#pragma unroll
            for (int rh = 0; rh < 2; rh++) {
                int lm = wid * 16 + rh * 8 + g;
                int ch = Gc + 2 * (m0 + lm);   // stays < NN even on partial tiles
#pragma unroll
                for (int dh = 0; dh < 2; dh++) {
                    int dd = dp * 16 + dh * 8 + i * 2;
                    if (czero) {
                        pcl[rh][dh] = make_float2(0.f, 0.f);
                        pcr[rh][dh] = make_float2(0.f, 0.f);
                    } else {
                        pcl[rh][dh] = *(const float2*)(g_c + (size_t)ch * DM + dd);
                        pcr[rh][dh] = *(const float2*)(g_c + (size_t)(ch + 1) * DM + dd);
                    }
                }
            }

            float acc[5][2][4];
#pragma unroll
            for (int q = 0; q < 5; q++)
#pragma unroll
                for (int dh = 0; dh < 2; dh++)
#pragma unroll
                    for (int c = 0; c < 4; c++) acc[q][dh][c] = 0.f;

#pragma unroll
            for (int pr = 0; pr < 8; pr++) {
                uint4 a0 = *(const uint4*)(A + arow + (uint32_t)pr * 64u);
                uint4 a1 = *(const uint4*)(A + arow + 8u * 512u + (uint32_t)pr * 64u);
                uint32_t f0[4] = {a0.x, a1.x, a0.y, a1.y};
                uint32_t f1[4] = {a0.z, a1.z, a0.w, a1.w};
#pragma unroll
                for (int q = 0; q < 5; q++) {
#pragma unroll
                    for (int dh = 0; dh < 2; dh++) {
                        uint4 b = *(const uint4*)(sB + (q * 16 + dh * 8 + g) * SBSTR
                                                  + i * 16 + pr * 64);
                        MMA(acc[q][dh], f0, b.x, b.y);
                        MMA(acc[q][dh], f1, b.z, b.w);
                    }
                }
            }

            // epilogue: thread covers rows {g, g+8} x dims {dh*8 + 2i, +1}
#pragma unroll
            for (int rh = 0; rh < 2; rh++) {
                int lm = wid * 16 + rh * 8 + g;
                if (m0 + lm >= M) continue;
                int node = s + m0 + lm;
                int local = m0 + lm;
                int b = local >> cshift;
                int jj = local & ((1 << cshift) - 1);
                size_t orow = ((size_t)(b * 1024 + offl + jj)) * DM;
#pragma unroll
                for (int dh = 0; dh < 2; dh++) {
                    int dd = dp * 16 + dh * 8 + i * 2;
                    float2 cl = pcl[rh][dh], cr = pcr[rh][dh];
                    float hv[2], cv[2];
#pragma unroll
                    for (int e = 0; e < 2; e++) {
                        float gi = acc[0][dh][rh * 2 + e] + sBB[0 * 128 + dd + e];
                        float go = acc[1][dh][rh * 2 + e] + sBB[1 * 128 + dd + e];
                        float gu = acc[2][dh][rh * 2 + e] + sBB[2 * 128 + dd + e];
                        float gl = acc[3][dh][rh * 2 + e] + sBB[3 * 128 + dd + e];
                        float gr = acc[4][dh][rh * 2 + e] + sBB[4 * 128 + dd + e];
                        float clv = e ? cl.y : cl.x;
                        float crv = e ? cr.y : cr.x;
                        float c = sigf(gi) * tanhapx(gu)
                                + sigf(gl) * clv + sigf(gr) * crv;
                        cv[e] = c;
                        hv[e] = sigf(go) * tanhapx(c);
                    }
                    *(float2*)(g_c + (size_t)node * DM + dd) = make_float2(cv[0], cv[1]);
                    *(__half2*)(g_h + (size_t)node * DM + dd) =
                        __floats2half2_rn(hv[0], hv[1]);
                    *(float2*)(out + orow + dd) = make_float2(hv[0], hv[1]);
                }
            }
            produce(l, tm >> 1);
        }
    }

    // ---- unary top level: 64 nodes; wait for all 8 level-9 tiles
    if (cta < 64) {
        consume(9, 0, 8u);
        float* xh = (float*)sB;                // B tile dead by now
        int ch = 65408 + cta;
        if (t < 128) xh[t] = __half2float(g_h[ch * DM + t]);
        __syncthreads();
        if (t < 128) {
            float acc[4] = {0.f, 0.f, 0.f, 0.f};
            for (int k = 0; k < 128; k++) {
                float x = xh[k];
#pragma unroll
                for (int q = 0; q < 4; q++) acc[q] += x * Wu[k * 512 + q * 128 + t];
            }
            float cc = g_c[ch * DM + t];
            float gi = acc[0] + bu[t];
            float go = acc[1] + bu[128 + t];
            float gu = acc[2] + bu[256 + t];
            float gf = acc[3] + bu[384 + t];
            float c = sigf(gi) * tanhapx(gu) + sigf(gf) * cc;
            float h = sigf(go) * tanhapx(c);
            out[((size_t)(cta * 1024 + 1023)) * DM + t] = h;
        }
    }
}

// ---------------------------------------------------------------------------
// kernel_launch: ONE kernel launch (graph-capturable, replay-deterministic)
// ---------------------------------------------------------------------------
extern "C" void kernel_launch(void* const* d_in, const int* in_sizes, int n_in,
                              void* d_out, int out_size) {
    const int* tokens = (const int*)d_in[0];
    const float* emb  = (const float*)d_in[3];
    const float* Wu   = (const float*)d_in[4];
    const float* bu   = (const float*)d_in[5];
    const float* Wb   = (const float*)d_in[6];
    const float* bb   = (const float*)d_in[7];
    float* out = (float*)d_out;

    fused<<<NC, 256>>>(tokens, emb, Wu, bu, Wb, bb, out);
}